// round 16
// baseline (speedup 1.0000x reference)
#include <cuda_runtime.h>
#include <cuda_bf16.h>
#include <cstdint>
#include <math.h>

#define N_NODES 100000
#define D 128
#define RREL 3
#define E_EDGES 600000
#define TILES64 ((N_NODES + 63) / 64)   // 1563
#define TOT3N (3 * N_NODES)
#define STAGE_BYTES 98304               // 96KB per pipeline stage
#define NBLK ((TOT3N + 1023) / 1024)    // 293 scan blocks
#define FLAG_AGG (1 << 30)
#define FLAG_INC (2 << 30)
#define VAL_MASK ((1 << 30) - 1)

// Scratch: static device globals (no allocation allowed).
// A tiles: [rel][tile] 64x128 bf16 in final swizzled layout (16KB = 4096 u32)
__device__ uint32_t g_Ah[(size_t)RREL * TILES64 * 4096];
__device__ uint32_t g_Al[(size_t)RREL * TILES64 * 4096];
__device__ float    g_deg[(size_t)2 * RREL * N_NODES]; // [2r]=deg_out_r, [2r+1]=deg_in_r
__device__ uint32_t g_Bh[RREL * 8192];                 // W_r^T bf16 hi, pre-swizzled (32KB/rel)
__device__ uint32_t g_Bl[RREL * 8192];                 // W_r^T bf16 lo, pre-swizzled
__device__ int      g_off[TOT3N + 1];                  // CSR offsets (concat over relations)
__device__ int      g_cursor[TOT3N];                   // fill cursors
__device__ int      g_state[NBLK];                     // decoupled-lookback states
__device__ uint2    g_edges[RREL * E_EDGES];           // {src, rsqrt_out[src]} CSR by dst
__device__ float    g_bsum[D];                         // b0+b1+b2

// ---------------------------------------------------------------------------
// Helpers
// ---------------------------------------------------------------------------
__device__ __forceinline__ uint32_t smem_u32(const void* p) {
    uint32_t a;
    asm("{ .reg .u64 t; cvta.to.shared.u64 t, %1; cvt.u32.u64 %0, t; }"
        : "=r"(a) : "l"(p));
    return a;
}

__device__ __forceinline__ void ldm4(uint32_t r[4], uint32_t addr) {
    asm volatile("ldmatrix.sync.aligned.m8n8.x4.shared.b16 {%0,%1,%2,%3}, [%4];"
                 : "=r"(r[0]), "=r"(r[1]), "=r"(r[2]), "=r"(r[3]) : "r"(addr));
}

__device__ __forceinline__ void mma_bf16(float c[4], const uint32_t a[4],
                                         uint32_t b0, uint32_t b1) {
    asm volatile(
        "mma.sync.aligned.m16n8k16.row.col.f32.bf16.bf16.f32 "
        "{%0,%1,%2,%3}, {%4,%5,%6,%7}, {%8,%9}, {%0,%1,%2,%3};"
        : "+f"(c[0]), "+f"(c[1]), "+f"(c[2]), "+f"(c[3])
        : "r"(a[0]), "r"(a[1]), "r"(a[2]), "r"(a[3]), "r"(b0), "r"(b1));
}

__device__ __forceinline__ void stcs2(uint32_t* p, uint32_t a, uint32_t b) {
    asm volatile("st.global.cs.v2.b32 [%0], {%1,%2};"
                 :: "l"(p), "r"(a), "r"(b) : "memory");
}

__device__ __forceinline__ void cp16(uint32_t s, const void* g) {
    asm volatile("cp.async.cg.shared.global [%0], [%1], 16;"
                 :: "r"(s), "l"(g) : "memory");
}

// ---------------------------------------------------------------------------
// Fused init: blocks [0, NZB) zero the degree array; blocks [NZB, NZB+3)
// convert W_r (pre-swizzled bf16 hi/lo) + bias sum; block NZB+3 zeroes
// the scan lookback states.
// ---------------------------------------------------------------------------
#define NZB ((2 * RREL * N_NODES / 4 + 255) / 256)   // 586 blocks for degrees

__global__ __launch_bounds__(256) void init_kernel(
    const float* __restrict__ W0, const float* __restrict__ W1,
    const float* __restrict__ W2,
    const float* __restrict__ b0, const float* __restrict__ b1,
    const float* __restrict__ b2)
{
    int blk = blockIdx.x;
    if (blk < NZB) {
        int i = blk * 256 + threadIdx.x;
        if (i < (2 * RREL * N_NODES) / 4)
            ((float4*)g_deg)[i] = make_float4(0.f, 0.f, 0.f, 0.f);
        return;
    }
    if (blk == NZB + RREL) {
        for (int i = threadIdx.x; i < NBLK; i += 256) g_state[i] = 0;
        return;
    }
    // W conversion: one block per relation, threads 0..127 active
    int r = blk - NZB;
    int n = threadIdx.x;
    if (n >= D) return;
    const float* W = (r == 0) ? W0 : ((r == 1) ? W1 : W2);
    if (r == 0) g_bsum[n] = b0[n] + b1[n] + b2[n];
    __nv_bfloat16* bh = (__nv_bfloat16*)(g_Bh + (size_t)r * 8192);
    __nv_bfloat16* bl = (__nv_bfloat16*)(g_Bl + (size_t)r * 8192);
    uint32_t rowoff = (uint32_t)n * 128u;  // bf16 units per row
    uint32_t rsw = (uint32_t)(n & 7);
#pragma unroll 4
    for (int k = 0; k < D; k++) {
        float w = W[(size_t)k * D + n];
        __nv_bfloat16 h = __float2bfloat16(w);
        __nv_bfloat16 l = __float2bfloat16(w - __bfloat162float(h));
        uint32_t off = rowoff + ((((uint32_t)(k >> 3)) ^ rsw) << 3) + (uint32_t)(k & 7);
        bh[off] = h;
        bl[off] = l;
    }
}

// ---------------------------------------------------------------------------
// Degree counting: 2 edges per thread (MLP on the atomic chains)
// ---------------------------------------------------------------------------
__global__ __launch_bounds__(256) void degree_kernel(
    const int* __restrict__ s0, const int* __restrict__ d0,
    const int* __restrict__ s1, const int* __restrict__ d1,
    const int* __restrict__ s2, const int* __restrict__ d2)
{
    int e = (blockIdx.x * 256 + threadIdx.x) * 2;
    if (e >= E_EDGES) return;
    int r = blockIdx.y;
    const int* sp = (r == 0) ? s0 : ((r == 1) ? s1 : s2);
    const int* dp = (r == 0) ? d0 : ((r == 1) ? d1 : d2);
    float* degOut = g_deg + (size_t)(2 * r) * N_NODES;
    float* degIn  = g_deg + (size_t)(2 * r + 1) * N_NODES;
    int sA = __ldg(sp + e), dA = __ldg(dp + e);
    bool hasB = (e + 1 < E_EDGES);
    int sB = hasB ? __ldg(sp + e + 1) : 0;
    int dB = hasB ? __ldg(dp + e + 1) : 0;
    atomicAdd(degOut + sA, 1.0f);
    atomicAdd(degIn + dA, 1.0f);
    if (hasB) {
        atomicAdd(degOut + sB, 1.0f);
        atomicAdd(degIn + dB, 1.0f);
    }
}

// ---------------------------------------------------------------------------
// Single-pass exclusive scan of concatenated deg_in with decoupled lookback.
// Also zeroes the fill cursors and writes g_off[TOT3N].
// ---------------------------------------------------------------------------
__global__ __launch_bounds__(256) void scan_kernel() {
    __shared__ int warpsum[8];
    __shared__ int s_excl;
    int tid = threadIdx.x;
    int bid = blockIdx.x;
    int base = bid * 1024 + tid * 4;
    int v[4];
#pragma unroll
    for (int j = 0; j < 4; j++) {
        int idx = base + j;
        int val = 0;
        if (idx < TOT3N) {
            int r = idx / N_NODES;
            int i = idx - r * N_NODES;
            val = (int)(g_deg[(size_t)(2 * r + 1) * N_NODES + i] + 0.5f);
        }
        v[j] = val;
    }
    int s = v[0] + v[1] + v[2] + v[3];
    int lane = tid & 31, wid = tid >> 5;
    int inc = s;
#pragma unroll
    for (int dlt = 1; dlt < 32; dlt <<= 1) {
        int t = __shfl_up_sync(0xffffffffu, inc, dlt);
        if (lane >= dlt) inc += t;
    }
    if (lane == 31) warpsum[wid] = inc;
    __syncthreads();
    if (wid == 0) {
        int ws = (lane < 8) ? warpsum[lane] : 0;
#pragma unroll
        for (int dlt = 1; dlt < 8; dlt <<= 1) {
            int t = __shfl_up_sync(0xffffffffu, ws, dlt);
            if (lane >= dlt) ws += t;
        }
        if (lane < 8) warpsum[lane] = ws;
    }
    __syncthreads();

    // decoupled lookback (thread 0)
    if (tid == 0) {
        int S = warpsum[7];   // block total
        int excl = 0;
        if (bid == 0) {
            atomicExch(&g_state[0], S | FLAG_INC);
        } else {
            atomicExch(&g_state[bid], S | FLAG_AGG);
            int i = bid - 1;
            while (true) {
                int st = atomicAdd(&g_state[i], 0);
                if (st & FLAG_INC) { excl += st & VAL_MASK; break; }
                if (st & FLAG_AGG) { excl += st & VAL_MASK; i--; }
            }
            atomicExch(&g_state[bid], (excl + S) | FLAG_INC);
        }
        if (bid == NBLK - 1) g_off[TOT3N] = excl + S;
        s_excl = excl;
    }
    __syncthreads();

    int warpbase = (wid > 0) ? warpsum[wid - 1] : 0;
    int run = s_excl + warpbase + inc - s;
#pragma unroll
    for (int j = 0; j < 4; j++) {
        int idx = base + j;
        if (idx < TOT3N) {
            g_off[idx] = run;
            g_cursor[idx] = 0;
        }
        run += v[j];
    }
}

// ---------------------------------------------------------------------------
// Fill CSR edge lists: g_edges[pos] = {src, rsqrt_out_r[src]}, key (rel,dst)
// Two edges per thread for MLP on the random deg/off reads.
// ---------------------------------------------------------------------------
__global__ __launch_bounds__(256) void fill_kernel(
    const int* __restrict__ s0, const int* __restrict__ d0,
    const int* __restrict__ s1, const int* __restrict__ d1,
    const int* __restrict__ s2, const int* __restrict__ d2)
{
    int e = (blockIdx.x * 256 + threadIdx.x) * 2;
    if (e >= E_EDGES) return;
    int r = blockIdx.y;
    const int* sp = (r == 0) ? s0 : ((r == 1) ? s1 : s2);
    const int* dp = (r == 0) ? d0 : ((r == 1) ? d1 : d2);

    int sA = __ldg(sp + e);
    int dA = __ldg(dp + e);
    bool hasB = (e + 1 < E_EDGES);
    int sB = hasB ? __ldg(sp + e + 1) : 0;
    int dB = hasB ? __ldg(dp + e + 1) : 0;

    float doutA = g_deg[(size_t)(2 * r) * N_NODES + sA];
    float doutB = hasB ? g_deg[(size_t)(2 * r) * N_NODES + sB] : 1.0f;
    float cA = rsqrtf(fmaxf(doutA, 1.0f));
    float cB = rsqrtf(fmaxf(doutB, 1.0f));

    int idxA = r * N_NODES + dA;
    int posA = g_off[idxA] + atomicAdd(&g_cursor[idxA], 1);
    g_edges[posA] = make_uint2((uint32_t)sA, __float_as_uint(cA));
    if (hasB) {
        int idxB = r * N_NODES + dB;
        int posB = g_off[idxB] + atomicAdd(&g_cursor[idxB], 1);
        g_edges[posB] = make_uint2((uint32_t)sB, __float_as_uint(cB));
    }
}

// ---------------------------------------------------------------------------
// Gather over raw x (L2-resident 51MB): one warp per node, 4-edge unroll.
// deg_in derived from CSR offsets (end - beg) — no g_deg read here.
// Result converted to bf16 hi/lo, stored directly in swizzled tile layout
// (evict-first; GEMM streams them later).
// ---------------------------------------------------------------------------
__global__ __launch_bounds__(256) void gather_kernel(const float* __restrict__ X)
{
    int w = (blockIdx.x * 256 + threadIdx.x) >> 5;
    if (w >= N_NODES) return;
    int lane = threadIdx.x & 31;
    const float4* x4 = (const float4*)X;

    const int t = w >> 6, lr = w & 63;
    const uint32_t woff = (uint32_t)lr * 64u
                        + ((((uint32_t)(lane >> 1)) ^ (uint32_t)(lr & 7)) << 2)
                        + (uint32_t)(lane & 1) * 2u;

#pragma unroll
    for (int r = 0; r < RREL; r++) {
        int idx = r * N_NODES + w;
        int beg = __ldg(&g_off[idx]);
        int end = __ldg(&g_off[idx + 1]);
        float4 acc = make_float4(0.f, 0.f, 0.f, 0.f);
        int j = beg;
        for (; j + 3 < end; j += 4) {
            uint2 e0 = __ldg(&g_edges[j]);
            uint2 e1 = __ldg(&g_edges[j + 1]);
            uint2 e2 = __ldg(&g_edges[j + 2]);
            uint2 e3 = __ldg(&g_edges[j + 3]);
            float4 v0 = x4[(size_t)e0.x * 32 + lane];
            float4 v1 = x4[(size_t)e1.x * 32 + lane];
            float4 v2 = x4[(size_t)e2.x * 32 + lane];
            float4 v3 = x4[(size_t)e3.x * 32 + lane];
            float c0 = __uint_as_float(e0.y), c1 = __uint_as_float(e1.y);
            float c2 = __uint_as_float(e2.y), c3 = __uint_as_float(e3.y);
            acc.x += c0 * v0.x + c1 * v1.x + c2 * v2.x + c3 * v3.x;
            acc.y += c0 * v0.y + c1 * v1.y + c2 * v2.y + c3 * v3.y;
            acc.z += c0 * v0.z + c1 * v1.z + c2 * v2.z + c3 * v3.z;
            acc.w += c0 * v0.w + c1 * v1.w + c2 * v2.w + c3 * v3.w;
        }
        for (; j < end; j++) {
            uint2 e0 = __ldg(&g_edges[j]);
            float4 v0 = x4[(size_t)e0.x * 32 + lane];
            float c0 = __uint_as_float(e0.y);
            acc.x += c0 * v0.x;
            acc.y += c0 * v0.y;
            acc.z += c0 * v0.z;
            acc.w += c0 * v0.w;
        }
        // deg_in == end - beg (offsets are the prefix sum of deg_in)
        float ci = rsqrtf(fmaxf((float)(end - beg), 1.0f));
        acc.x *= ci; acc.y *= ci; acc.z *= ci; acc.w *= ci;

        __nv_bfloat16 h0 = __float2bfloat16(acc.x);
        __nv_bfloat16 h1 = __float2bfloat16(acc.y);
        __nv_bfloat16 h2 = __float2bfloat16(acc.z);
        __nv_bfloat16 h3 = __float2bfloat16(acc.w);
        __nv_bfloat16 l0 = __float2bfloat16(acc.x - __bfloat162float(h0));
        __nv_bfloat16 l1 = __float2bfloat16(acc.y - __bfloat162float(h1));
        __nv_bfloat16 l2 = __float2bfloat16(acc.z - __bfloat162float(h2));
        __nv_bfloat16 l3 = __float2bfloat16(acc.w - __bfloat162float(h3));
        __nv_bfloat162 ph0 = {h0, h1}, ph1 = {h2, h3};
        __nv_bfloat162 pl0 = {l0, l1}, pl1 = {l2, l3};

        size_t base = ((size_t)r * TILES64 + t) * 4096 + woff;
        stcs2(g_Ah + base, *(uint32_t*)&ph0, *(uint32_t*)&ph1);
        stcs2(g_Al + base, *(uint32_t*)&pl0, *(uint32_t*)&pl1);
    }
}

// ---------------------------------------------------------------------------
// Issue cp.async copies for one (tile, rel) unit into a pipeline stage.
// Stage layout: Ah[16K] Al[16K] Bh[32K] Bl[32K].
// ---------------------------------------------------------------------------
__device__ __forceinline__ void issue_unit(uint32_t sb, int tile, int r, int tid)
{
    const uint4* srcAh = (const uint4*)(g_Ah + ((size_t)r * TILES64 + tile) * 4096);
    const uint4* srcAl = (const uint4*)(g_Al + ((size_t)r * TILES64 + tile) * 4096);
#pragma unroll
    for (int j = 0; j < 4; j++) {                // 1024 uint4 each
        int f = tid + j * 256;
        cp16(sb + f * 16, srcAh + f);
        cp16(sb + 16384 + f * 16, srcAl + f);
    }
    const uint4* srcBh = (const uint4*)(g_Bh + (size_t)r * 8192);
    const uint4* srcBl = (const uint4*)(g_Bl + (size_t)r * 8192);
#pragma unroll
    for (int j = 0; j < 8; j++) {                // 2048 uint4 each
        int f = tid + j * 256;
        cp16(sb + 32768 + f * 16, srcBh + f);
        cp16(sb + 65536 + f * 16, srcBl + f);
    }
    asm volatile("cp.async.commit_group;" ::: "memory");
}

// ---------------------------------------------------------------------------
// PERSISTENT pipelined HMMA GEMM (K=384): out = relu( sum_r A_r @ B_r + bsum )
// Grid = 148 CTAs (1/SM), 256 threads, 192KB smem = 2 x 96KB stages.
// Unit = (tile, rel). cp.async prefetches unit u+1 while MMA consumes unit u.
// ---------------------------------------------------------------------------
__global__ __launch_bounds__(256, 1) void gemm_hmma_kernel(float* __restrict__ out)
{
    extern __shared__ char sm[];
    uint32_t sbase = smem_u32(sm);

    const int tid = threadIdx.x;
    const int wid = tid >> 5;
    const int lane = tid & 31;

    const int m0 = (wid & 3) * 16;
    const int n0 = (wid >> 2) * 64;
    const int t7 = lane & 7;
    const uint32_t dkc = (uint32_t)(lane >> 4);
    const int rsel = ((lane >> 3) & 1) * 8;
    const uint32_t aRowBase = (uint32_t)(m0 + t7 + rsel) * 256u;
    const uint32_t bRowBase = (uint32_t)(n0 + t7 + rsel) * 256u;
    const uint32_t rsw = (uint32_t)t7;

    const int first = blockIdx.x;
    const int nt = (TILES64 - first + 147) / 148;   // tiles this CTA owns
    const int nunits = nt * 3;
    if (nt <= 0) return;

    float C[8][4];

    issue_unit(sbase, first, 0, tid);

#pragma unroll 1
    for (int u = 0; u < nunits; u++) {
        int tile = first + (u / 3) * 148;
        int r = u - (u / 3) * 3;

        if (u + 1 < nunits) {
            int u1 = u + 1;
            issue_unit(sbase + (uint32_t)(u1 & 1) * STAGE_BYTES,
                       first + (u1 / 3) * 148, u1 - (u1 / 3) * 3, tid);
            asm volatile("cp.async.wait_group 1;" ::: "memory");
        } else {
            asm volatile("cp.async.wait_group 0;" ::: "memory");
        }
        __syncthreads();

        uint32_t sb = sbase + (uint32_t)(u & 1) * STAGE_BYTES;
        const uint32_t sXh = sb;
        const uint32_t sXl = sb + 16384;
        const uint32_t sBh = sb + 32768;
        const uint32_t sBl = sb + 65536;

        if (r == 0) {
#pragma unroll
            for (int nj = 0; nj < 8; nj++)
#pragma unroll
                for (int q = 0; q < 4; q++) C[nj][q] = 0.f;
        }

#pragma unroll
        for (int kk = 0; kk < 8; kk++) {
            uint32_t chunk = (((uint32_t)(kk * 2) + dkc) ^ rsw) << 4;
            uint32_t ah[4], al[4], bh[16], bl[16];
            ldm4(ah, sXh + aRowBase + chunk);
            ldm4(al, sXl + aRowBase + chunk);
#pragma unroll
            for (int p = 0; p < 4; p++) {
                ldm4(bh + 4 * p, sBh + bRowBase + (uint32_t)p * 4096 + chunk);
                ldm4(bl + 4 * p, sBl + bRowBase + (uint32_t)p * 4096 + chunk);
            }
#pragma unroll
            for (int p = 0; p < 4; p++) {
                mma_bf16(C[2 * p],     ah, bh[4 * p],     bh[4 * p + 2]);
                mma_bf16(C[2 * p + 1], ah, bh[4 * p + 1], bh[4 * p + 3]);
                mma_bf16(C[2 * p],     ah, bl[4 * p],     bl[4 * p + 2]);
                mma_bf16(C[2 * p + 1], ah, bl[4 * p + 1], bl[4 * p + 3]);
                mma_bf16(C[2 * p],     al, bh[4 * p],     bh[4 * p + 2]);
                mma_bf16(C[2 * p + 1], al, bh[4 * p + 1], bh[4 * p + 3]);
            }
        }

        if (r == 2) {
            int gm0 = tile * 64 + m0;
            int row0 = gm0 + (lane >> 2);
            int row1 = row0 + 8;
#pragma unroll
            for (int nj = 0; nj < 8; nj++) {
                int col = n0 + nj * 8 + (lane & 3) * 2;
                float b0v = g_bsum[col], b1v = g_bsum[col + 1];
                if (row0 < N_NODES) {
                    float2 v = {fmaxf(C[nj][0] + b0v, 0.f), fmaxf(C[nj][1] + b1v, 0.f)};
                    *(float2*)(out + (size_t)row0 * D + col) = v;
                }
                if (row1 < N_NODES) {
                    float2 v = {fmaxf(C[nj][2] + b0v, 0.f), fmaxf(C[nj][3] + b1v, 0.f)};
                    *(float2*)(out + (size_t)row1 * D + col) = v;
                }
            }
        }
        __syncthreads();   // all warps done reading stage (u&1) before u+2 overwrites it
    }
}

// ---------------------------------------------------------------------------
// Launcher
// ---------------------------------------------------------------------------
extern "C" void kernel_launch(void* const* d_in, const int* in_sizes, int n_in,
                              void* d_out, int out_size)
{
    const float* x = nullptr;
    const float* Wp[RREL] = {nullptr, nullptr, nullptr};
    const float* bp[RREL] = {nullptr, nullptr, nullptr};
    const int*   ep[2 * RREL] = {nullptr};
    int wi = 0, bi = 0, ei = 0;

    for (int i = 0; i < n_in; i++) {
        int sz = in_sizes[i];
        if (sz == N_NODES * D)      x = (const float*)d_in[i];
        else if (sz == D * D)       { if (wi < RREL) Wp[wi++] = (const float*)d_in[i]; }
        else if (sz == D)           { if (bi < RREL) bp[bi++] = (const float*)d_in[i]; }
        else if (sz == E_EDGES)     { if (ei < 2 * RREL) ep[ei++] = (const int*)d_in[i]; }
    }

    float* out = (float*)d_out;
    const int GEMM_SMEM = 2 * STAGE_BYTES;  // 192KB, 1 CTA/SM
    cudaFuncSetAttribute(gemm_hmma_kernel,
                         cudaFuncAttributeMaxDynamicSharedMemorySize, GEMM_SMEM);

    // 1. fused init: zero degrees + convert W + bias sum + zero scan states
    init_kernel<<<NZB + RREL + 1, 256>>>(Wp[0], Wp[1], Wp[2], bp[0], bp[1], bp[2]);

    // 2. degrees (2 edges/thread)
    {
        dim3 grid((E_EDGES / 2 + 255) / 256, RREL);
        degree_kernel<<<grid, 256>>>(ep[0], ep[1], ep[2], ep[3], ep[4], ep[5]);
    }

    // 3. CSR offsets: single-pass decoupled-lookback scan (also zeros cursors)
    scan_kernel<<<NBLK, 256>>>();

    // 4. fill CSR edges (2 edges/thread)
    {
        dim3 grid((E_EDGES / 2 + 255) / 256, RREL);
        fill_kernel<<<grid, 256>>>(ep[0], ep[1], ep[2], ep[3], ep[4], ep[5]);
    }

    // 5. gather over x (L2-resident) -> pre-swizzled bf16 A tiles
    {
        int blocks = (int)(((long long)N_NODES * 32 + 255) / 256);
        gather_kernel<<<blocks, 256>>>(x);
    }

    // 6. persistent pipelined GEMM + bias + relu -> out
    gemm_hmma_kernel<<<148, 256, GEMM_SMEM>>>(out);
}

// round 17
// speedup vs baseline: 1.0292x; 1.0292x over previous
#include <cuda_runtime.h>
#include <cuda_bf16.h>
#include <cstdint>
#include <math.h>

#define N_NODES 100000
#define D 128
#define RREL 3
#define E_EDGES 600000
#define TILES64 ((N_NODES + 63) / 64)   // 1563
#define TOT3N (3 * N_NODES)
#define STAGE_BYTES 98304               // 96KB per pipeline stage

// Scratch: static device globals (no allocation allowed).
// A tiles: [rel][tile] 64x128 bf16 in final swizzled layout (16KB = 4096 u32)
__device__ uint32_t g_Ah[(size_t)RREL * TILES64 * 4096];
__device__ uint32_t g_Al[(size_t)RREL * TILES64 * 4096];
__device__ int      g_degout[RREL * N_NODES];          // out-degree (int)
__device__ int      g_degin[RREL * N_NODES];           // in-degree (int, concat layout)
__device__ int      g_rank[RREL * E_EDGES];            // edge rank within dst list
__device__ uint32_t g_Bh[RREL * 8192];                 // W_r^T bf16 hi, pre-swizzled (32KB/rel)
__device__ uint32_t g_Bl[RREL * 8192];                 // W_r^T bf16 lo, pre-swizzled
__device__ int      g_off[TOT3N + 1];                  // CSR offsets (concat over relations)
__device__ int      g_blk[512];                        // scan block sums
__device__ uint2    g_edges[RREL * E_EDGES];           // {src, rsqrt_out[src]} CSR by dst
__device__ float    g_bsum[D];                         // b0+b1+b2

// ---------------------------------------------------------------------------
// Helpers
// ---------------------------------------------------------------------------
__device__ __forceinline__ uint32_t smem_u32(const void* p) {
    uint32_t a;
    asm("{ .reg .u64 t; cvta.to.shared.u64 t, %1; cvt.u32.u64 %0, t; }"
        : "=r"(a) : "l"(p));
    return a;
}

__device__ __forceinline__ void ldm4(uint32_t r[4], uint32_t addr) {
    asm volatile("ldmatrix.sync.aligned.m8n8.x4.shared.b16 {%0,%1,%2,%3}, [%4];"
                 : "=r"(r[0]), "=r"(r[1]), "=r"(r[2]), "=r"(r[3]) : "r"(addr));
}

__device__ __forceinline__ void mma_bf16(float c[4], const uint32_t a[4],
                                         uint32_t b0, uint32_t b1) {
    asm volatile(
        "mma.sync.aligned.m16n8k16.row.col.f32.bf16.bf16.f32 "
        "{%0,%1,%2,%3}, {%4,%5,%6,%7}, {%8,%9}, {%0,%1,%2,%3};"
        : "+f"(c[0]), "+f"(c[1]), "+f"(c[2]), "+f"(c[3])
        : "r"(a[0]), "r"(a[1]), "r"(a[2]), "r"(a[3]), "r"(b0), "r"(b1));
}

__device__ __forceinline__ void stcs2(uint32_t* p, uint32_t a, uint32_t b) {
    asm volatile("st.global.cs.v2.b32 [%0], {%1,%2};"
                 :: "l"(p), "r"(a), "r"(b) : "memory");
}

__device__ __forceinline__ void cp16(uint32_t s, const void* g) {
    asm volatile("cp.async.cg.shared.global [%0], [%1], 16;"
                 :: "r"(s), "l"(g) : "memory");
}

// ---------------------------------------------------------------------------
// Fused init: blocks [0, NZB) zero the degree arrays; blocks [NZB, NZB+3)
// convert W_r -> transposed bf16 hi/lo (pre-swizzled) + bias sum.
// ---------------------------------------------------------------------------
#define NZB ((2 * RREL * N_NODES / 4 + 255) / 256)   // 586 blocks for degrees

__global__ __launch_bounds__(256) void init_kernel(
    const float* __restrict__ W0, const float* __restrict__ W1,
    const float* __restrict__ W2,
    const float* __restrict__ b0, const float* __restrict__ b1,
    const float* __restrict__ b2)
{
    int blk = blockIdx.x;
    if (blk < NZB) {
        int i = blk * 256 + threadIdx.x;
        const int half = (RREL * N_NODES) / 4;   // 75000 int4 per array
        if (i < half) {
            ((int4*)g_degout)[i] = make_int4(0, 0, 0, 0);
            ((int4*)g_degin)[i] = make_int4(0, 0, 0, 0);
        }
        return;
    }
    // W conversion: one block per relation, threads 0..127 active
    int r = blk - NZB;
    int n = threadIdx.x;
    if (n >= D) return;
    const float* W = (r == 0) ? W0 : ((r == 1) ? W1 : W2);
    if (r == 0) g_bsum[n] = b0[n] + b1[n] + b2[n];
    __nv_bfloat16* bh = (__nv_bfloat16*)(g_Bh + (size_t)r * 8192);
    __nv_bfloat16* bl = (__nv_bfloat16*)(g_Bl + (size_t)r * 8192);
    uint32_t rowoff = (uint32_t)n * 128u;  // bf16 units per row
    uint32_t rsw = (uint32_t)(n & 7);
#pragma unroll 4
    for (int k = 0; k < D; k++) {
        float w = W[(size_t)k * D + n];
        __nv_bfloat16 h = __float2bfloat16(w);
        __nv_bfloat16 l = __float2bfloat16(w - __bfloat162float(h));
        uint32_t off = rowoff + ((((uint32_t)(k >> 3)) ^ rsw) << 3) + (uint32_t)(k & 7);
        bh[off] = h;
        bl[off] = l;
    }
}

// ---------------------------------------------------------------------------
// Degree counting + per-edge rank capture.
// rank = old value of deg_in[dst] — later reused as the edge's slot within
// its dst's CSR segment (removes all atomics from fill_kernel).
// ---------------------------------------------------------------------------
__global__ __launch_bounds__(256) void degree_kernel(
    const int* __restrict__ s0, const int* __restrict__ d0,
    const int* __restrict__ s1, const int* __restrict__ d1,
    const int* __restrict__ s2, const int* __restrict__ d2)
{
    int e = blockIdx.x * 256 + threadIdx.x;
    if (e >= E_EDGES) return;
    int r = blockIdx.y;
    const int* sp = (r == 0) ? s0 : ((r == 1) ? s1 : s2);
    const int* dp = (r == 0) ? d0 : ((r == 1) ? d1 : d2);
    int s = __ldg(sp + e);
    int d = __ldg(dp + e);
    atomicAdd(&g_degout[r * N_NODES + s], 1);
    int rank = atomicAdd(&g_degin[r * N_NODES + d], 1);
    g_rank[r * E_EDGES + e] = rank;
}

// ---------------------------------------------------------------------------
// Scan pass 1: per-block (1024 elems) exclusive scan of concatenated deg_in
// ---------------------------------------------------------------------------
__global__ __launch_bounds__(256) void scan1_kernel() {
    __shared__ int warpsum[8];
    int tid = threadIdx.x;
    int base = blockIdx.x * 1024 + tid * 4;
    int v[4];
#pragma unroll
    for (int j = 0; j < 4; j++) {
        int idx = base + j;
        v[j] = (idx < TOT3N) ? g_degin[idx] : 0;
    }
    int s = v[0] + v[1] + v[2] + v[3];
    int lane = tid & 31, wid = tid >> 5;
    int inc = s;
#pragma unroll
    for (int dlt = 1; dlt < 32; dlt <<= 1) {
        int t = __shfl_up_sync(0xffffffffu, inc, dlt);
        if (lane >= dlt) inc += t;
    }
    if (lane == 31) warpsum[wid] = inc;
    __syncthreads();
    if (wid == 0) {
        int ws = (lane < 8) ? warpsum[lane] : 0;
#pragma unroll
        for (int dlt = 1; dlt < 8; dlt <<= 1) {
            int t = __shfl_up_sync(0xffffffffu, ws, dlt);
            if (lane >= dlt) ws += t;
        }
        if (lane < 8) warpsum[lane] = ws;
    }
    __syncthreads();
    int warpbase = (wid > 0) ? warpsum[wid - 1] : 0;
    int run = warpbase + inc - s;
#pragma unroll
    for (int j = 0; j < 4; j++) {
        int idx = base + j;
        if (idx < TOT3N) g_off[idx] = run;
        run += v[j];
    }
    if (tid == 255) g_blk[blockIdx.x] = warpsum[7];
}

// ---------------------------------------------------------------------------
// Scan pass 2: exclusive scan of block sums (nblk <= 512), single block
// ---------------------------------------------------------------------------
__global__ __launch_bounds__(512) void scan2_kernel(int nblk) {
    __shared__ int sh[512];
    int tid = threadIdx.x;
    sh[tid] = (tid < nblk) ? g_blk[tid] : 0;
    __syncthreads();
#pragma unroll
    for (int dlt = 1; dlt < 512; dlt <<= 1) {
        int t = (tid >= dlt) ? sh[tid - dlt] : 0;
        __syncthreads();
        sh[tid] += t;
        __syncthreads();
    }
    if (tid < nblk) g_blk[tid] = (tid > 0) ? sh[tid - 1] : 0;
    if (tid == 0) g_off[TOT3N] = sh[511];
}

// ---------------------------------------------------------------------------
// Scan pass 3: add block offsets
// ---------------------------------------------------------------------------
__global__ __launch_bounds__(256) void scan3_kernel() {
    int i = blockIdx.x * 256 + threadIdx.x;
    if (i < TOT3N) g_off[i] += g_blk[i >> 10];
}

// ---------------------------------------------------------------------------
// Fill CSR edge lists: ATOMIC-FREE. pos = off[rel,dst] + rank[e].
// Two edges per thread for MLP on the random off/deg reads.
// ---------------------------------------------------------------------------
__global__ __launch_bounds__(256) void fill_kernel(
    const int* __restrict__ s0, const int* __restrict__ d0,
    const int* __restrict__ s1, const int* __restrict__ d1,
    const int* __restrict__ s2, const int* __restrict__ d2)
{
    int e = (blockIdx.x * 256 + threadIdx.x) * 2;
    if (e >= E_EDGES) return;
    int r = blockIdx.y;
    const int* sp = (r == 0) ? s0 : ((r == 1) ? s1 : s2);
    const int* dp = (r == 0) ? d0 : ((r == 1) ? d1 : d2);

    int sA = __ldg(sp + e);
    int dA = __ldg(dp + e);
    int rkA = g_rank[r * E_EDGES + e];
    bool hasB = (e + 1 < E_EDGES);
    int sB = hasB ? __ldg(sp + e + 1) : 0;
    int dB = hasB ? __ldg(dp + e + 1) : 0;
    int rkB = hasB ? g_rank[r * E_EDGES + e + 1] : 0;

    int doutA = g_degout[r * N_NODES + sA];
    int doutB = hasB ? g_degout[r * N_NODES + sB] : 1;
    int offA = g_off[r * N_NODES + dA];
    int offB = hasB ? g_off[r * N_NODES + dB] : 0;

    float cA = rsqrtf(fmaxf((float)doutA, 1.0f));
    float cB = rsqrtf(fmaxf((float)doutB, 1.0f));

    g_edges[offA + rkA] = make_uint2((uint32_t)sA, __float_as_uint(cA));
    if (hasB)
        g_edges[offB + rkB] = make_uint2((uint32_t)sB, __float_as_uint(cB));
}

// ---------------------------------------------------------------------------
// Gather over raw x (L2-resident 51MB): one warp per node, 4-edge unroll.
// deg_in derived from CSR offsets (end - beg) — no degree read here.
// Result converted to bf16 hi/lo, stored directly in swizzled tile layout
// (evict-first; GEMM streams them later).
// ---------------------------------------------------------------------------
__global__ __launch_bounds__(256) void gather_kernel(const float* __restrict__ X)
{
    int w = (blockIdx.x * 256 + threadIdx.x) >> 5;
    if (w >= N_NODES) return;
    int lane = threadIdx.x & 31;
    const float4* x4 = (const float4*)X;

    const int t = w >> 6, lr = w & 63;
    const uint32_t woff = (uint32_t)lr * 64u
                        + ((((uint32_t)(lane >> 1)) ^ (uint32_t)(lr & 7)) << 2)
                        + (uint32_t)(lane & 1) * 2u;

#pragma unroll
    for (int r = 0; r < RREL; r++) {
        int idx = r * N_NODES + w;
        int beg = __ldg(&g_off[idx]);
        int end = __ldg(&g_off[idx + 1]);
        float4 acc = make_float4(0.f, 0.f, 0.f, 0.f);
        int j = beg;
        for (; j + 3 < end; j += 4) {
            uint2 e0 = __ldg(&g_edges[j]);
            uint2 e1 = __ldg(&g_edges[j + 1]);
            uint2 e2 = __ldg(&g_edges[j + 2]);
            uint2 e3 = __ldg(&g_edges[j + 3]);
            float4 v0 = x4[(size_t)e0.x * 32 + lane];
            float4 v1 = x4[(size_t)e1.x * 32 + lane];
            float4 v2 = x4[(size_t)e2.x * 32 + lane];
            float4 v3 = x4[(size_t)e3.x * 32 + lane];
            float c0 = __uint_as_float(e0.y), c1 = __uint_as_float(e1.y);
            float c2 = __uint_as_float(e2.y), c3 = __uint_as_float(e3.y);
            acc.x += c0 * v0.x + c1 * v1.x + c2 * v2.x + c3 * v3.x;
            acc.y += c0 * v0.y + c1 * v1.y + c2 * v2.y + c3 * v3.y;
            acc.z += c0 * v0.z + c1 * v1.z + c2 * v2.z + c3 * v3.z;
            acc.w += c0 * v0.w + c1 * v1.w + c2 * v2.w + c3 * v3.w;
        }
        for (; j < end; j++) {
            uint2 e0 = __ldg(&g_edges[j]);
            float4 v0 = x4[(size_t)e0.x * 32 + lane];
            float c0 = __uint_as_float(e0.y);
            acc.x += c0 * v0.x;
            acc.y += c0 * v0.y;
            acc.z += c0 * v0.z;
            acc.w += c0 * v0.w;
        }
        // deg_in == end - beg (offsets are the prefix sum of deg_in)
        float ci = rsqrtf(fmaxf((float)(end - beg), 1.0f));
        acc.x *= ci; acc.y *= ci; acc.z *= ci; acc.w *= ci;

        __nv_bfloat16 h0 = __float2bfloat16(acc.x);
        __nv_bfloat16 h1 = __float2bfloat16(acc.y);
        __nv_bfloat16 h2 = __float2bfloat16(acc.z);
        __nv_bfloat16 h3 = __float2bfloat16(acc.w);
        __nv_bfloat16 l0 = __float2bfloat16(acc.x - __bfloat162float(h0));
        __nv_bfloat16 l1 = __float2bfloat16(acc.y - __bfloat162float(h1));
        __nv_bfloat16 l2 = __float2bfloat16(acc.z - __bfloat162float(h2));
        __nv_bfloat16 l3 = __float2bfloat16(acc.w - __bfloat162float(h3));
        __nv_bfloat162 ph0 = {h0, h1}, ph1 = {h2, h3};
        __nv_bfloat162 pl0 = {l0, l1}, pl1 = {l2, l3};

        size_t base = ((size_t)r * TILES64 + t) * 4096 + woff;
        stcs2(g_Ah + base, *(uint32_t*)&ph0, *(uint32_t*)&ph1);
        stcs2(g_Al + base, *(uint32_t*)&pl0, *(uint32_t*)&pl1);
    }
}

// ---------------------------------------------------------------------------
// Issue cp.async copies for one (tile, rel) unit into a pipeline stage.
// Stage layout: Ah[16K] Al[16K] Bh[32K] Bl[32K].
// ---------------------------------------------------------------------------
__device__ __forceinline__ void issue_unit(uint32_t sb, int tile, int r, int tid)
{
    const uint4* srcAh = (const uint4*)(g_Ah + ((size_t)r * TILES64 + tile) * 4096);
    const uint4* srcAl = (const uint4*)(g_Al + ((size_t)r * TILES64 + tile) * 4096);
#pragma unroll
    for (int j = 0; j < 4; j++) {                // 1024 uint4 each
        int f = tid + j * 256;
        cp16(sb + f * 16, srcAh + f);
        cp16(sb + 16384 + f * 16, srcAl + f);
    }
    const uint4* srcBh = (const uint4*)(g_Bh + (size_t)r * 8192);
    const uint4* srcBl = (const uint4*)(g_Bl + (size_t)r * 8192);
#pragma unroll
    for (int j = 0; j < 8; j++) {                // 2048 uint4 each
        int f = tid + j * 256;
        cp16(sb + 32768 + f * 16, srcBh + f);
        cp16(sb + 65536 + f * 16, srcBl + f);
    }
    asm volatile("cp.async.commit_group;" ::: "memory");
}

// ---------------------------------------------------------------------------
// PERSISTENT pipelined HMMA GEMM (K=384): out = relu( sum_r A_r @ B_r + bsum )
// Grid = 148 CTAs (1/SM), 256 threads, 192KB smem = 2 x 96KB stages.
// Unit = (tile, rel). cp.async prefetches unit u+1 while MMA consumes unit u.
// ---------------------------------------------------------------------------
__global__ __launch_bounds__(256, 1) void gemm_hmma_kernel(float* __restrict__ out)
{
    extern __shared__ char sm[];
    uint32_t sbase = smem_u32(sm);

    const int tid = threadIdx.x;
    const int wid = tid >> 5;
    const int lane = tid & 31;

    const int m0 = (wid & 3) * 16;
    const int n0 = (wid >> 2) * 64;
    const int t7 = lane & 7;
    const uint32_t dkc = (uint32_t)(lane >> 4);
    const int rsel = ((lane >> 3) & 1) * 8;
    const uint32_t aRowBase = (uint32_t)(m0 + t7 + rsel) * 256u;
    const uint32_t bRowBase = (uint32_t)(n0 + t7 + rsel) * 256u;
    const uint32_t rsw = (uint32_t)t7;

    const int first = blockIdx.x;
    const int nt = (TILES64 - first + 147) / 148;   // tiles this CTA owns
    const int nunits = nt * 3;
    if (nt <= 0) return;

    float C[8][4];

    issue_unit(sbase, first, 0, tid);

#pragma unroll 1
    for (int u = 0; u < nunits; u++) {
        int tile = first + (u / 3) * 148;
        int r = u - (u / 3) * 3;

        if (u + 1 < nunits) {
            int u1 = u + 1;
            issue_unit(sbase + (uint32_t)(u1 & 1) * STAGE_BYTES,
                       first + (u1 / 3) * 148, u1 - (u1 / 3) * 3, tid);
            asm volatile("cp.async.wait_group 1;" ::: "memory");
        } else {
            asm volatile("cp.async.wait_group 0;" ::: "memory");
        }
        __syncthreads();

        uint32_t sb = sbase + (uint32_t)(u & 1) * STAGE_BYTES;
        const uint32_t sXh = sb;
        const uint32_t sXl = sb + 16384;
        const uint32_t sBh = sb + 32768;
        const uint32_t sBl = sb + 65536;

        if (r == 0) {
#pragma unroll
            for (int nj = 0; nj < 8; nj++)
#pragma unroll
                for (int q = 0; q < 4; q++) C[nj][q] = 0.f;
        }

#pragma unroll
        for (int kk = 0; kk < 8; kk++) {
            uint32_t chunk = (((uint32_t)(kk * 2) + dkc) ^ rsw) << 4;
            uint32_t ah[4], al[4], bh[16], bl[16];
            ldm4(ah, sXh + aRowBase + chunk);
            ldm4(al, sXl + aRowBase + chunk);
#pragma unroll
            for (int p = 0; p < 4; p++) {
                ldm4(bh + 4 * p, sBh + bRowBase + (uint32_t)p * 4096 + chunk);
                ldm4(bl + 4 * p, sBl + bRowBase + (uint32_t)p * 4096 + chunk);
            }
#pragma unroll
            for (int p = 0; p < 4; p++) {
                mma_bf16(C[2 * p],     ah, bh[4 * p],     bh[4 * p + 2]);
                mma_bf16(C[2 * p + 1], ah, bh[4 * p + 1], bh[4 * p + 3]);
                mma_bf16(C[2 * p],     ah, bl[4 * p],     bl[4 * p + 2]);
                mma_bf16(C[2 * p + 1], ah, bl[4 * p + 1], bl[4 * p + 3]);
                mma_bf16(C[2 * p],     al, bh[4 * p],     bh[4 * p + 2]);
                mma_bf16(C[2 * p + 1], al, bh[4 * p + 1], bh[4 * p + 3]);
            }
        }

        if (r == 2) {
            int gm0 = tile * 64 + m0;
            int row0 = gm0 + (lane >> 2);
            int row1 = row0 + 8;
#pragma unroll
            for (int nj = 0; nj < 8; nj++) {
                int col = n0 + nj * 8 + (lane & 3) * 2;
                float b0v = g_bsum[col], b1v = g_bsum[col + 1];
                if (row0 < N_NODES) {
                    float2 v = {fmaxf(C[nj][0] + b0v, 0.f), fmaxf(C[nj][1] + b1v, 0.f)};
                    *(float2*)(out + (size_t)row0 * D + col) = v;
                }
                if (row1 < N_NODES) {
                    float2 v = {fmaxf(C[nj][2] + b0v, 0.f), fmaxf(C[nj][3] + b1v, 0.f)};
                    *(float2*)(out + (size_t)row1 * D + col) = v;
                }
            }
        }
        __syncthreads();   // all warps done reading stage (u&1) before u+2 overwrites it
    }
}

// ---------------------------------------------------------------------------
// Launcher
// ---------------------------------------------------------------------------
extern "C" void kernel_launch(void* const* d_in, const int* in_sizes, int n_in,
                              void* d_out, int out_size)
{
    const float* x = nullptr;
    const float* Wp[RREL] = {nullptr, nullptr, nullptr};
    const float* bp[RREL] = {nullptr, nullptr, nullptr};
    const int*   ep[2 * RREL] = {nullptr};
    int wi = 0, bi = 0, ei = 0;

    for (int i = 0; i < n_in; i++) {
        int sz = in_sizes[i];
        if (sz == N_NODES * D)      x = (const float*)d_in[i];
        else if (sz == D * D)       { if (wi < RREL) Wp[wi++] = (const float*)d_in[i]; }
        else if (sz == D)           { if (bi < RREL) bp[bi++] = (const float*)d_in[i]; }
        else if (sz == E_EDGES)     { if (ei < 2 * RREL) ep[ei++] = (const int*)d_in[i]; }
    }

    float* out = (float*)d_out;
    const int GEMM_SMEM = 2 * STAGE_BYTES;  // 192KB, 1 CTA/SM
    cudaFuncSetAttribute(gemm_hmma_kernel,
                         cudaFuncAttributeMaxDynamicSharedMemorySize, GEMM_SMEM);

    // 1. fused init: zero degrees + convert W (pre-swizzled) + bias sum
    init_kernel<<<NZB + RREL, 256>>>(Wp[0], Wp[1], Wp[2], bp[0], bp[1], bp[2]);

    // 2. degrees + per-edge rank capture
    {
        dim3 grid((E_EDGES + 255) / 256, RREL);
        degree_kernel<<<grid, 256>>>(ep[0], ep[1], ep[2], ep[3], ep[4], ep[5]);
    }

    // 3. CSR offsets: 3-pass scan over concatenated deg_in
    const int NBLK = (TOT3N + 1023) / 1024;  // 293
    scan1_kernel<<<NBLK, 256>>>();
    scan2_kernel<<<1, 512>>>(NBLK);
    scan3_kernel<<<(TOT3N + 255) / 256, 256>>>();

    // 4. fill CSR edges (atomic-free: off + rank)
    {
        dim3 grid((E_EDGES / 2 + 255) / 256, RREL);
        fill_kernel<<<grid, 256>>>(ep[0], ep[1], ep[2], ep[3], ep[4], ep[5]);
    }

    // 5. gather over x (L2-resident) -> pre-swizzled bf16 A tiles
    {
        int blocks = (int)(((long long)N_NODES * 32 + 255) / 256);
        gather_kernel<<<blocks, 256>>>(x);
    }

    // 6. persistent pipelined GEMM + bias + relu -> out
    gemm_hmma_kernel<<<148, 256, GEMM_SMEM>>>(out);
}